// round 2
// baseline (speedup 1.0000x reference)
#include <cuda_runtime.h>
#include <cstdint>
#include <cstddef>

// ---------------- problem constants ----------------
#define NIMG   16
#define CIN    256
#define COUT   512
#define HIN    128
#define OHB    129            // blurred spatial size (129x129)
#define SPLITW 64             // columns per parity-split plane
#define SPLANE (OHB*SPLITW)   // 8256 floats per (n,c) split plane

// GEMM tiling
#define BM 128
#define BN 128
#define BK 32
#define SPITCH 132            // smem row pitch (conflict-free: 132 % 32 = 4)
#define NCHUNK 72             // K = 9 taps * 256 c = 2304 = 72 * 32

// ---------------- device scratch (no allocs allowed) ----------------
// Blurred input, tf32-rounded, split by output-column phase so that the
// implicit-GEMM A loads are unit-stride and 16B-aligned for every tap t:
//   t=0 -> col 2q   -> xbE [q]
//   t=1 -> col 2q+1 -> xbO [q]
//   t=2 -> col 2q+2 -> xbE2[q]
__device__ float g_xbE [(size_t)NIMG*CIN*SPLANE];
__device__ float g_xbO [(size_t)NIMG*CIN*SPLANE];
__device__ float g_xbE2[(size_t)NIMG*CIN*SPLANE];
// Weights repacked to [tap(9)][c(256)][oc(512)], scaled by 1/sqrt(fan_in), tf32-rounded
__device__ float g_Bw[9*CIN*COUT];

__device__ __forceinline__ float tf32r(float x){
    uint32_t u; asm("cvt.rna.tf32.f32 %0, %1;" : "=r"(u) : "f"(x));
    return __uint_as_float(u);
}

// ---------------- kernel 1: separable 4x4 blur, pad=2 ----------------
// Each thread: one (plane, x-column), 4 vertically adjacent outputs.
// blur_k is rank-1 (outer(k,k)/sum), so K[a][b] = R[a]*C[b] with
// C[b]=K[0][b], R[a]=K[a][0]/K[0][0].
__global__ void blur_kernel(const float* __restrict__ x, const float* __restrict__ bk){
    const unsigned XG = 129, YG = 33;  // 33*4 >= 129 rows
    unsigned id = blockIdx.x * blockDim.x + threadIdx.x;
    const unsigned total = (unsigned)NIMG*CIN*YG*XG;
    if (id >= total) return;
    unsigned xc    = id % XG;
    unsigned r     = id / XG;
    unsigned yg    = r % YG;
    unsigned plane = r / YG;

    float C0=__ldg(bk+0), C1=__ldg(bk+1), C2=__ldg(bk+2), C3=__ldg(bk+3);
    float inv = 1.0f / C0;
    float R1=__ldg(bk+4)*inv, R2=__ldg(bk+8)*inv, R3=__ldg(bk+12)*inv;

    const float* xp = x + (size_t)plane * (HIN*HIN);
    int y0 = (int)yg * 4;
    int cb = (int)xc - 2;

    float cs[7];
    #pragma unroll
    for (int rr = 0; rr < 7; rr++){
        int row = y0 - 2 + rr;
        float v = 0.f;
        if (row >= 0 && row < HIN){
            const float* rp = xp + row*HIN;
            float a0 = (cb+0 >= 0 && cb+0 < HIN) ? __ldg(rp+cb+0) : 0.f;
            float a1 = (cb+1 >= 0 && cb+1 < HIN) ? __ldg(rp+cb+1) : 0.f;
            float a2 = (cb+2 >= 0 && cb+2 < HIN) ? __ldg(rp+cb+2) : 0.f;
            float a3 = (cb+3 >= 0 && cb+3 < HIN) ? __ldg(rp+cb+3) : 0.f;
            v = a0*C0 + a1*C1 + a2*C2 + a3*C3;
        }
        cs[rr] = v;
    }

    float* pe  = g_xbE  + (size_t)plane * SPLANE;
    float* po  = g_xbO  + (size_t)plane * SPLANE;
    float* pe2 = g_xbE2 + (size_t)plane * SPLANE;
    #pragma unroll
    for (int i = 0; i < 4; i++){
        int y = y0 + i;
        if (y < OHB){
            float v = cs[i] + R1*cs[i+1] + R2*cs[i+2] + R3*cs[i+3];
            v = tf32r(v);
            unsigned rb = (unsigned)y * SPLITW;
            if ((xc & 1u) == 0u){
                unsigned h = xc >> 1;
                if (h < SPLITW) pe[rb + h] = v;       // tap t=0 view
                if (xc >= 2)    pe2[rb + h - 1] = v;  // tap t=2 view (shifted)
            } else {
                po[rb + (xc >> 1)] = v;               // tap t=1 view
            }
        }
    }
}

// ---------------- kernel 2: weight repack [tap][c][oc], scaled, tf32 ----------------
__global__ void wtrans_kernel(const float* __restrict__ w){
    int id = blockIdx.x * blockDim.x + threadIdx.x;
    if (id >= 9*CIN*COUT) return;
    int oc  = id & (COUT-1);
    int rem = id >> 9;
    int c   = rem & (CIN-1);
    int tap = rem >> 8;
    int s = tap / 3, t = tap - 3*s;
    const float scale = 0.0208333333333333333f;  // 1/48 = 1/sqrt(256*9)
    float v = w[((size_t)(oc*CIN + c)*3 + s)*3 + t] * scale;
    g_Bw[id] = tf32r(v);
}

// ---------------- kernel 3: implicit GEMM conv (tf32 mma.sync) ----------------
__device__ __forceinline__ void mma_tf32(float c[4], const uint32_t a[4], const uint32_t b[2]){
    asm volatile(
        "mma.sync.aligned.m16n8k8.row.col.f32.tf32.tf32.f32 "
        "{%0,%1,%2,%3}, {%4,%5,%6,%7}, {%8,%9}, {%0,%1,%2,%3};\n"
        : "+f"(c[0]), "+f"(c[1]), "+f"(c[2]), "+f"(c[3])
        : "r"(a[0]), "r"(a[1]), "r"(a[2]), "r"(a[3]), "r"(b[0]), "r"(b[1]));
}

__device__ __forceinline__ void load_chunk(
    int chunk, int stage, int warp, int lane,
    int nimg, int p, int q, int n0, uint32_t sA, uint32_t sB)
{
    int tap = chunk >> 3;
    int cb  = (chunk & 7) << 5;           // c base within tap
    int s   = tap / 3;
    int t   = tap - 3*s;
    const float* ab = (t == 0) ? g_xbE : (t == 1 ? g_xbO : g_xbE2);
    int row = 2*p + s;                    // 0..128
    const float* asrc0 = ab + (size_t)nimg*CIN*SPLANE + (size_t)row*SPLITW + q;
    int mA = lane * 4;

    #pragma unroll
    for (int i = 0; i < 4; i++){
        int kl = i*8 + warp;              // 0..31
        const float* src = asrc0 + (size_t)(cb + kl) * SPLANE;
        uint32_t dst = sA + (uint32_t)(((stage*BK + kl)*SPITCH + mA) << 2);
        asm volatile("cp.async.cg.shared.global [%0], [%1], 16;\n" :: "r"(dst), "l"(src));
    }
    int nl = lane * 4;
    const float* bsrc0 = g_Bw + (((size_t)tap*CIN + cb) << 9) + n0 + nl;
    #pragma unroll
    for (int i = 0; i < 4; i++){
        int kl = i*8 + warp;
        const float* src = bsrc0 + ((size_t)kl << 9);
        uint32_t dst = sB + (uint32_t)(((stage*BK + kl)*SPITCH + nl) << 2);
        asm volatile("cp.async.cg.shared.global [%0], [%1], 16;\n" :: "r"(dst), "l"(src));
    }
}

__global__ void __launch_bounds__(256, 2)
conv_kernel(const float* __restrict__ bias, float* __restrict__ out){
    extern __shared__ float smem[];
    float* As = smem;                  // [2][BK][SPITCH]
    float* Bs = smem + 2*BK*SPITCH;    // [2][BK][SPITCH]

    const int tid  = threadIdx.x;
    const int lane = tid & 31, warp = tid >> 5;
    const int m0   = blockIdx.y * BM;
    const int n0   = blockIdx.x * BN;
    const int nimg = m0 >> 12;                      // 4096 pixels per image
    const int g    = lane >> 2, tig = lane & 3;
    const int wm   = warp & 3,  wn  = warp >> 2;    // 4x2 warp grid -> 32x64 warp tile

    const int mA = lane * 4;
    const int p  = ((m0 + mA) >> 6) & 63;
    const int q  = mA & 63;

    uint32_t sA = (uint32_t)__cvta_generic_to_shared(As);
    uint32_t sB = (uint32_t)__cvta_generic_to_shared(Bs);

    float acc[2][8][4];
    #pragma unroll
    for (int i = 0; i < 2; i++)
        #pragma unroll
        for (int j = 0; j < 8; j++)
            #pragma unroll
            for (int k = 0; k < 4; k++) acc[i][j][k] = 0.f;

    load_chunk(0, 0, warp, lane, nimg, p, q, n0, sA, sB);
    asm volatile("cp.async.commit_group;\n" ::);

    for (int ch = 0; ch < NCHUNK; ch++){
        int st = ch & 1;
        if (ch + 1 < NCHUNK){
            load_chunk(ch + 1, st ^ 1, warp, lane, nimg, p, q, n0, sA, sB);
            asm volatile("cp.async.commit_group;\n" ::);
            asm volatile("cp.async.wait_group 1;\n" ::);
        } else {
            asm volatile("cp.async.wait_group 0;\n" ::);
        }
        __syncthreads();

        const float* Ab = As + st*BK*SPITCH;
        const float* Bb = Bs + st*BK*SPITCH;
        #pragma unroll
        for (int ks = 0; ks < 4; ks++){
            uint32_t af[2][4], bf[8][2];
            const float* Ak0 = Ab + (ks*8 + tig    )*SPITCH;
            const float* Ak1 = Ab + (ks*8 + tig + 4)*SPITCH;
            #pragma unroll
            for (int mt = 0; mt < 2; mt++){
                int mr = wm*32 + mt*16 + g;
                af[mt][0] = __float_as_uint(Ak0[mr]);
                af[mt][1] = __float_as_uint(Ak0[mr + 8]);
                af[mt][2] = __float_as_uint(Ak1[mr]);
                af[mt][3] = __float_as_uint(Ak1[mr + 8]);
            }
            const float* Bk0 = Bb + (ks*8 + tig    )*SPITCH;
            const float* Bk1 = Bb + (ks*8 + tig + 4)*SPITCH;
            #pragma unroll
            for (int nt = 0; nt < 8; nt++){
                int nc = wn*64 + nt*8 + g;
                bf[nt][0] = __float_as_uint(Bk0[nc]);
                bf[nt][1] = __float_as_uint(Bk1[nc]);
            }
            #pragma unroll
            for (int mt = 0; mt < 2; mt++)
                #pragma unroll
                for (int nt = 0; nt < 8; nt++)
                    mma_tf32(acc[mt][nt], af[mt], bf[nt]);
        }
        __syncthreads();
    }

    // epilogue: y[n][oc][p][q] += bias
    #pragma unroll
    for (int mt = 0; mt < 2; mt++){
        int r0 = m0 + wm*32 + mt*16 + g;
        size_t mb = (size_t)(r0 & 4095);
        #pragma unroll
        for (int nt = 0; nt < 8; nt++){
            int oc = n0 + wn*64 + nt*8 + 2*tig;
            float b0 = __ldg(bias + oc), b1 = __ldg(bias + oc + 1);
            size_t base = (((size_t)(nimg*COUT + oc)) << 12) + mb;
            out[base           ] = acc[mt][nt][0] + b0;  // (r0,   oc  )
            out[base + 4096    ] = acc[mt][nt][1] + b1;  // (r0,   oc+1)
            out[base + 8       ] = acc[mt][nt][2] + b0;  // (r0+8, oc  )
            out[base + 4096 + 8] = acc[mt][nt][3] + b1;  // (r0+8, oc+1)
        }
    }
}

// ---------------- launch ----------------
extern "C" void kernel_launch(void* const* d_in, const int* in_sizes, int n_in,
                              void* d_out, int out_size){
    const float* x    = (const float*)d_in[0];   // [16,256,128,128]
    const float* w    = (const float*)d_in[1];   // [512,256,3,3]
    const float* bias = (const float*)d_in[2];   // [512]
    const float* bk   = (const float*)d_in[3];   // [4,4]
    float* out = (float*)d_out;                  // [16,512,64,64]
    (void)in_sizes; (void)n_in; (void)out_size;

    {   // blur: 4096 planes * 33 y-groups * 129 x
        long total = (long)NIMG*CIN*33*129;
        int blocks = (int)((total + 255) / 256);
        blur_kernel<<<blocks, 256>>>(x, bk);
    }
    wtrans_kernel<<<(9*CIN*COUT + 255)/256, 256>>>(w);

    const int SMEM = 2 * (2*BK*SPITCH) * 4;  // 67584 bytes
    cudaFuncSetAttribute(conv_kernel, cudaFuncAttributeMaxDynamicSharedMemorySize, SMEM);
    conv_kernel<<<dim3(BN == 128 ? COUT/BN : 4, (NIMG*64*64)/BM), 256, SMEM>>>(bias, out);
}

// round 4
// speedup vs baseline: 1.3206x; 1.3206x over previous
#include <cuda_runtime.h>
#include <cstdint>
#include <cstddef>

// ---------------- problem constants ----------------
#define NIMG   16
#define CIN    256
#define COUT   512
#define HIN    128
#define OHB    129
#define SPLITW 64
#define SPLANE (OHB*SPLITW)

#define KTOT   2304
#define NCHUNK 72            // 2304 / 32
// GEMM tiling
#define BM 256               // pixels per block
#define BN 128               // output channels per block
#define BK 32
#define APITCH 264           // floats; 264 % 32 == 8 -> conflict-free frag loads
#define BPITCH 136           // 136 % 32 == 8
#define NSTAGE 4
#define A_STAGE_F (BK*APITCH)              // 8448 floats
#define B_STAGE_F (BK*BPITCH)              // 4352 floats
#define STAGE_F   (A_STAGE_F + B_STAGE_F)  // 12800 floats = 51200 B

// ---------------- device scratch ----------------
__device__ float g_xbE [(size_t)NIMG*CIN*SPLANE];
__device__ float g_xbO [(size_t)NIMG*CIN*SPLANE];
__device__ float g_xbE2[(size_t)NIMG*CIN*SPLANE];
__device__ float g_Bw[9*CIN*COUT];   // [tap][c][oc], scaled, tf32-rounded

__device__ __forceinline__ float tf32r(float x){
    uint32_t u; asm("cvt.rna.tf32.f32 %0, %1;" : "=r"(u) : "f"(x));
    return __uint_as_float(u);
}

// ---------------- kernel 1: separable 4x4 blur (validated in R1/R2) ----------------
__global__ void blur_kernel(const float* __restrict__ x, const float* __restrict__ bk){
    const unsigned XG = 129, YG = 33;
    unsigned id = blockIdx.x * blockDim.x + threadIdx.x;
    const unsigned total = (unsigned)NIMG*CIN*YG*XG;
    if (id >= total) return;
    unsigned xc    = id % XG;
    unsigned r     = id / XG;
    unsigned yg    = r % YG;
    unsigned plane = r / YG;

    float C0=__ldg(bk+0), C1=__ldg(bk+1), C2=__ldg(bk+2), C3=__ldg(bk+3);
    float inv = 1.0f / C0;
    float R1=__ldg(bk+4)*inv, R2=__ldg(bk+8)*inv, R3=__ldg(bk+12)*inv;

    const float* xp = x + (size_t)plane * (HIN*HIN);
    int y0 = (int)yg * 4;
    int cb = (int)xc - 2;

    float cs[7];
    #pragma unroll
    for (int rr = 0; rr < 7; rr++){
        int row = y0 - 2 + rr;
        float v = 0.f;
        if (row >= 0 && row < HIN){
            const float* rp = xp + row*HIN;
            float a0 = (cb+0 >= 0 && cb+0 < HIN) ? __ldg(rp+cb+0) : 0.f;
            float a1 = (cb+1 >= 0 && cb+1 < HIN) ? __ldg(rp+cb+1) : 0.f;
            float a2 = (cb+2 >= 0 && cb+2 < HIN) ? __ldg(rp+cb+2) : 0.f;
            float a3 = (cb+3 >= 0 && cb+3 < HIN) ? __ldg(rp+cb+3) : 0.f;
            v = a0*C0 + a1*C1 + a2*C2 + a3*C3;
        }
        cs[rr] = v;
    }

    float* pe  = g_xbE  + (size_t)plane * SPLANE;
    float* po  = g_xbO  + (size_t)plane * SPLANE;
    float* pe2 = g_xbE2 + (size_t)plane * SPLANE;
    #pragma unroll
    for (int i = 0; i < 4; i++){
        int y = y0 + i;
        if (y < OHB){
            float v = cs[i] + R1*cs[i+1] + R2*cs[i+2] + R3*cs[i+3];
            v = tf32r(v);
            unsigned rb = (unsigned)y * SPLITW;
            if ((xc & 1u) == 0u){
                unsigned h = xc >> 1;
                if (h < SPLITW) pe[rb + h] = v;
                if (xc >= 2)    pe2[rb + h - 1] = v;
            } else {
                po[rb + (xc >> 1)] = v;
            }
        }
    }
}

// ---------------- kernel 2: weight repack [tap][c][oc], scaled, tf32 ----------------
__global__ void wtrans_kernel(const float* __restrict__ w){
    int id = blockIdx.x * blockDim.x + threadIdx.x;
    if (id >= 9*CIN*COUT) return;
    int oc  = id & (COUT-1);
    int rem = id >> 9;
    int c   = rem & (CIN-1);
    int tap = rem >> 8;
    int s = tap / 3, t = tap - 3*s;
    const float scale = 0.0208333333333333333f;  // 1/sqrt(2304)
    float v = w[((size_t)(oc*CIN + c)*3 + s)*3 + t] * scale;
    g_Bw[id] = tf32r(v);
}

// ---------------- kernel 3: implicit GEMM conv (tf32 mma.sync, 256x128 tile) ----------------
__device__ __forceinline__ void mma_tf32(float c[4], const uint32_t a[4], const uint32_t b[2]){
    asm volatile(
        "mma.sync.aligned.m16n8k8.row.col.f32.tf32.tf32.f32 "
        "{%0,%1,%2,%3}, {%4,%5,%6,%7}, {%8,%9}, {%0,%1,%2,%3};\n"
        : "+f"(c[0]), "+f"(c[1]), "+f"(c[2]), "+f"(c[3])
        : "r"(a[0]), "r"(a[1]), "r"(a[2]), "r"(a[3]), "r"(b[0]), "r"(b[1]));
}

#define CP16(dst, src) \
    asm volatile("cp.async.cg.shared.global [%0], [%1], 16;\n" :: "r"(dst), "l"(src))

__global__ void __launch_bounds__(256, 1)
conv_kernel(const float* __restrict__ bias, float* __restrict__ out){
    extern __shared__ float smem[];

    const int tid  = threadIdx.x;
    const int lane = tid & 31, warp = tid >> 5;
    const int n0   = blockIdx.x * BN;              // oc base
    const int m0   = blockIdx.y * BM;              // pixel base
    const int nimg = m0 >> 12;
    const int p0   = (m0 & 4095) >> 6;             // starting output row (4 rows per block)
    const int g    = lane >> 2, tig = lane & 3;
    const int wm   = warp & 3,  wn  = warp >> 2;   // 4x2 warps -> 64x64 warp tile

    const uint32_t sbase = (uint32_t)__cvta_generic_to_shared(smem);
    const size_t planeBase = (size_t)(nimg*CIN) * SPLANE;

    auto load_chunk = [&](int ch, int stage){
        const int tap = ch >> 3;
        const int cbs = (ch & 7) << 5;
        const int s   = tap / 3;
        const int t   = tap - 3*s;
        const float* ab = (t == 0) ? g_xbE : (t == 1 ? g_xbO : g_xbE2);
        const uint32_t stg = sbase + (uint32_t)stage * (STAGE_F*4);
        // A: pixels [32 k][256 m], m = p_local*64 + q
        #pragma unroll
        for (int i = 0; i < 8; i++){
            int gid = i*256 + tid;
            int k   = gid >> 6;           // 0..31
            int mg  = gid & 63;           // 16B granule within row
            int pl  = mg >> 4;            // 0..3
            int q4  = (mg & 15) << 2;
            const float* src = ab + planeBase + (size_t)(cbs + k)*SPLANE
                             + (size_t)(2*(p0 + pl) + s)*SPLITW + q4;
            CP16(stg + (uint32_t)((k*APITCH + mg*4) << 2), src);
        }
        // B: weights [32 k][128 oc]
        #pragma unroll
        for (int i = 0; i < 4; i++){
            int gid = i*256 + tid;
            int k   = gid >> 5;           // 0..31
            int ng  = gid & 31;
            const float* src = g_Bw + (((size_t)tap*CIN + cbs + k) << 9) + n0 + ng*4;
            CP16(stg + (uint32_t)((A_STAGE_F + k*BPITCH + ng*4) << 2), src);
        }
    };

    float acc[4][8][4];
    #pragma unroll
    for (int i = 0; i < 4; i++)
        #pragma unroll
        for (int j = 0; j < 8; j++)
            #pragma unroll
            for (int kk = 0; kk < 4; kk++) acc[i][j][kk] = 0.f;

    // prologue: 3 chunks in flight
    #pragma unroll
    for (int ch = 0; ch < NSTAGE-1; ch++){
        load_chunk(ch, ch);
        asm volatile("cp.async.commit_group;" ::: "memory");
    }

    for (int ch = 0; ch < NCHUNK; ch++){
        const int w = NCHUNK - 1 - ch;
        if (w >= 2)      asm volatile("cp.async.wait_group 2;" ::: "memory");
        else if (w == 1) asm volatile("cp.async.wait_group 1;" ::: "memory");
        else             asm volatile("cp.async.wait_group 0;" ::: "memory");
        __syncthreads();

        const int nxt = ch + NSTAGE - 1;
        if (nxt < NCHUNK){
            load_chunk(nxt, nxt & (NSTAGE-1));
            asm volatile("cp.async.commit_group;" ::: "memory");
        }

        const float* Ab = smem + (size_t)(ch & (NSTAGE-1)) * STAGE_F;
        const float* Bb = Ab + A_STAGE_F;
        #pragma unroll
        for (int ks = 0; ks < 4; ks++){
            uint32_t af[4][4], bf[8][2];
            const float* A0 = Ab + (ks*8 + tig    )*APITCH + wm*64;
            const float* A1 = Ab + (ks*8 + tig + 4)*APITCH + wm*64;
            #pragma unroll
            for (int mt = 0; mt < 4; mt++){
                int mr = mt*16 + g;
                af[mt][0] = __float_as_uint(A0[mr]);
                af[mt][1] = __float_as_uint(A0[mr + 8]);
                af[mt][2] = __float_as_uint(A1[mr]);
                af[mt][3] = __float_as_uint(A1[mr + 8]);
            }
            const float* B0 = Bb + (ks*8 + tig    )*BPITCH + wn*64;
            const float* B1 = Bb + (ks*8 + tig + 4)*BPITCH + wn*64;
            #pragma unroll
            for (int nt = 0; nt < 8; nt++){
                int nc = nt*8 + g;
                bf[nt][0] = __float_as_uint(B0[nc]);
                bf[nt][1] = __float_as_uint(B1[nc]);
            }
            #pragma unroll
            for (int mt = 0; mt < 4; mt++)
                #pragma unroll
                for (int nt = 0; nt < 8; nt++)
                    mma_tf32(acc[mt][nt], af[mt], bf[nt]);
        }
    }

    // epilogue
    #pragma unroll
    for (int mt = 0; mt < 4; mt++){
        int r0 = m0 + wm*64 + mt*16 + g;
        size_t mb = (size_t)(r0 & 4095);
        #pragma unroll
        for (int nt = 0; nt < 8; nt++){
            int oc = n0 + wn*64 + nt*8 + 2*tig;
            float b0 = __ldg(bias + oc), b1 = __ldg(bias + oc + 1);
            size_t base = (((size_t)(nimg*COUT + oc)) << 12) + mb;
            out[base           ] = acc[mt][nt][0] + b0;
            out[base + 4096    ] = acc[mt][nt][1] + b1;
            out[base + 8       ] = acc[mt][nt][2] + b0;
            out[base + 4096 + 8] = acc[mt][nt][3] + b1;
        }
    }
}

// ---------------- launch ----------------
extern "C" void kernel_launch(void* const* d_in, const int* in_sizes, int n_in,
                              void* d_out, int out_size){
    const float* x    = (const float*)d_in[0];
    const float* w    = (const float*)d_in[1];
    const float* bias = (const float*)d_in[2];
    const float* bk   = (const float*)d_in[3];
    float* out = (float*)d_out;
    (void)in_sizes; (void)n_in; (void)out_size;

    {
        long total = (long)NIMG*CIN*33*129;
        int blocks = (int)((total + 255) / 256);
        blur_kernel<<<blocks, 256>>>(x, bk);
    }
    wtrans_kernel<<<(9*CIN*COUT + 255)/256, 256>>>(w);

    const int SMEM = NSTAGE * STAGE_F * 4;  // 204800 bytes
    cudaFuncSetAttribute(conv_kernel, cudaFuncAttributeMaxDynamicSharedMemorySize, SMEM);
    conv_kernel<<<dim3(COUT/BN, (NIMG*64*64)/BM), 256, SMEM>>>(bias, out);
}

// round 6
// speedup vs baseline: 2.2022x; 1.6675x over previous
#include <cuda_runtime.h>
#include <cuda_fp16.h>
#include <cstdint>
#include <cstddef>

// ---------------- problem constants ----------------
#define NIMG   16
#define CIN    256
#define COUT   512
#define HIN    128
#define OHB    129
#define WPLANE (OHB*64)       // 8256 half2-words per (n, c-pair) plane
#define NPP    2048           // 16 images * 128 channel-pairs

#define NCHUNK 72             // K = 2304 channels*taps, 32 per chunk (16 pairs)
// GEMM tiling
#define BM 256                // pixels
#define BN 128                // output channels
#define APITCH 264            // words; 264 % 32 == 8 -> conflict-free
#define BPITCH 136            // words; 136 % 32 == 8
#define NSTAGE 8
#define A_STAGE_W (16*APITCH)              // 4224 words
#define B_STAGE_W (16*BPITCH)              // 2176 words
#define STAGE_W   (A_STAGE_W + B_STAGE_W)  // 6400 words = 25600 B

// ---------------- device scratch ----------------
// blurred pixels as half2 (channel-pair interleaved), 3 column-phase views
__device__ __align__(16) unsigned int g_xbE [(size_t)NPP*WPLANE];
__device__ __align__(16) unsigned int g_xbO [(size_t)NPP*WPLANE];
__device__ __align__(16) unsigned int g_xbE2[(size_t)NPP*WPLANE];
// weights as half2: [tap(9)][c-pair(128)][oc(512)]
__device__ __align__(16) unsigned int g_Bw[9*128*COUT];

// ---------------- kernel 1: separable 4x4 blur, channel-pair version ----------------
__global__ void blur_kernel(const float* __restrict__ x, const float* __restrict__ bk){
    const unsigned XG = 129, YG = 33;
    unsigned id = blockIdx.x * blockDim.x + threadIdx.x;
    const unsigned total = (unsigned)NPP*YG*XG;
    if (id >= total) return;
    unsigned xc = id % XG;
    unsigned r  = id / XG;
    unsigned yg = r % YG;
    unsigned pp = r / YG;            // plane-pair: n*128 + c2

    float C0=__ldg(bk+0), C1=__ldg(bk+1), C2=__ldg(bk+2), C3=__ldg(bk+3);
    float inv = 1.0f / C0;
    float R1=__ldg(bk+4)*inv, R2=__ldg(bk+8)*inv, R3=__ldg(bk+12)*inv;

    const float* xp0 = x + (size_t)pp * 2 * (HIN*HIN);
    const float* xp1 = xp0 + HIN*HIN;
    int y0 = (int)yg * 4;
    int cb = (int)xc - 2;

    float cs0[7], cs1[7];
    #pragma unroll
    for (int rr = 0; rr < 7; rr++){
        int row = y0 - 2 + rr;
        float v0 = 0.f, v1 = 0.f;
        if (row >= 0 && row < HIN){
            const float* rp0 = xp0 + row*HIN;
            const float* rp1 = xp1 + row*HIN;
            bool b0 = (cb+0 >= 0 && cb+0 < HIN);
            bool b1 = (cb+1 >= 0 && cb+1 < HIN);
            bool b2 = (cb+2 >= 0 && cb+2 < HIN);
            bool b3 = (cb+3 >= 0 && cb+3 < HIN);
            float p00 = b0 ? __ldg(rp0+cb+0) : 0.f;
            float p01 = b1 ? __ldg(rp0+cb+1) : 0.f;
            float p02 = b2 ? __ldg(rp0+cb+2) : 0.f;
            float p03 = b3 ? __ldg(rp0+cb+3) : 0.f;
            float p10 = b0 ? __ldg(rp1+cb+0) : 0.f;
            float p11 = b1 ? __ldg(rp1+cb+1) : 0.f;
            float p12 = b2 ? __ldg(rp1+cb+2) : 0.f;
            float p13 = b3 ? __ldg(rp1+cb+3) : 0.f;
            v0 = p00*C0 + p01*C1 + p02*C2 + p03*C3;
            v1 = p10*C0 + p11*C1 + p12*C2 + p13*C3;
        }
        cs0[rr] = v0; cs1[rr] = v1;
    }

    unsigned int* pe  = g_xbE  + (size_t)pp * WPLANE;
    unsigned int* po  = g_xbO  + (size_t)pp * WPLANE;
    unsigned int* pe2 = g_xbE2 + (size_t)pp * WPLANE;
    #pragma unroll
    for (int i = 0; i < 4; i++){
        int y = y0 + i;
        if (y < OHB){
            float v0 = cs0[i] + R1*cs0[i+1] + R2*cs0[i+2] + R3*cs0[i+3];
            float v1 = cs1[i] + R1*cs1[i+1] + R2*cs1[i+2] + R3*cs1[i+3];
            __half2 hv = __floats2half2_rn(v0, v1);
            unsigned int w = *reinterpret_cast<unsigned int*>(&hv);
            unsigned rb = (unsigned)y * 64;
            unsigned h  = xc >> 1;
            if ((xc & 1u) == 0u){
                if (h < 64) pe[rb + h] = w;
                if (xc >= 2) pe2[rb + h - 1] = w;
            } else {
                po[rb + h] = w;
            }
        }
    }
}

// ---------------- kernel 2: weight repack half2 [tap][c-pair][oc] ----------------
__global__ void wtrans_kernel(const float* __restrict__ w){
    unsigned id = blockIdx.x * blockDim.x + threadIdx.x;
    if (id >= 9u*128u*512u) return;
    unsigned oc  = id & 511u;
    unsigned kp  = (id >> 9) & 127u;
    unsigned tap = id >> 16;
    unsigned s = tap / 3, t = tap - 3*s;
    const float scale = 0.0208333333333333333f;  // 1/sqrt(2304)
    unsigned c0 = kp*2, c1 = kp*2 + 1;
    float v0 = __ldg(&w[((size_t)(oc*CIN + c0)*3 + s)*3 + t]) * scale;
    float v1 = __ldg(&w[((size_t)(oc*CIN + c1)*3 + s)*3 + t]) * scale;
    __half2 hv = __floats2half2_rn(v0, v1);
    g_Bw[id] = *reinterpret_cast<unsigned int*>(&hv);
}

// ---------------- kernel 3: implicit GEMM conv (fp16 mma, fp32 accum) ----------------
__device__ __forceinline__ void mma_f16(float c[4], const unsigned a[4], const unsigned b[2]){
    asm volatile(
        "mma.sync.aligned.m16n8k16.row.col.f32.f16.f16.f32 "
        "{%0,%1,%2,%3}, {%4,%5,%6,%7}, {%8,%9}, {%0,%1,%2,%3};\n"
        : "+f"(c[0]), "+f"(c[1]), "+f"(c[2]), "+f"(c[3])
        : "r"(a[0]), "r"(a[1]), "r"(a[2]), "r"(a[3]), "r"(b[0]), "r"(b[1]));
}

#define CP16(dst, src) \
    asm volatile("cp.async.cg.shared.global [%0], [%1], 16;\n" :: "r"(dst), "l"(src))

__global__ void __launch_bounds__(256, 1)
conv_kernel(const float* __restrict__ bias, float* __restrict__ out){
    extern __shared__ unsigned int smem[];

    const int tid  = threadIdx.x;
    const int lane = tid & 31, warp = tid >> 5;
    const int n0   = blockIdx.x * BN;
    const int m0   = blockIdx.y * BM;
    const int nimg = m0 >> 12;
    const int p0   = (m0 & 4095) >> 6;            // 4 output rows per block
    const int g    = lane >> 2, tig = lane & 3;
    const int wm   = warp & 3,  wn  = warp >> 2;  // 4x2 warps -> 64x64 warp tile

    const uint32_t sbase = (uint32_t)__cvta_generic_to_shared(smem);
    const size_t pb2 = (size_t)nimg * 128;        // plane-pair base for this image

    auto load_chunk = [&](int ch, int stage){
        const int tap = ch >> 3;
        const int cb2 = (ch & 7) << 4;            // c-pair base within tap (16 pairs/chunk)
        const int s   = tap / 3;
        const int t   = tap - 3*s;
        const unsigned int* ab = (t == 0) ? g_xbE : (t == 1 ? g_xbO : g_xbE2);
        const uint32_t stg = sbase + (uint32_t)stage * (STAGE_W*4);
        // A: pixels [16 kp][256 m] half2 words
        #pragma unroll
        for (int i = 0; i < 4; i++){
            int gid = i*256 + tid;
            int kp  = gid >> 6;                   // 0..15
            int mg  = gid & 63;                   // 16B granule (4 pixels)
            int pl  = mg >> 4;
            int q4  = (mg & 15) << 2;
            const unsigned int* src = ab + (pb2 + cb2 + kp)*WPLANE
                                    + (size_t)(2*(p0 + pl) + s)*64 + q4;
            CP16(stg + (uint32_t)((kp*APITCH + mg*4) << 2), src);
        }
        // B: weights [16 kp][128 oc] half2 words
        #pragma unroll
        for (int i = 0; i < 2; i++){
            int gid = i*256 + tid;
            int kp  = gid >> 5;                   // 0..15
            int ng  = gid & 31;
            const unsigned int* src = g_Bw + ((size_t)tap*128 + cb2 + kp)*COUT + n0 + ng*4;
            CP16(stg + (uint32_t)((A_STAGE_W + kp*BPITCH + ng*4) << 2), src);
        }
    };

    float acc[4][8][4];
    #pragma unroll
    for (int i = 0; i < 4; i++)
        #pragma unroll
        for (int j = 0; j < 8; j++)
            #pragma unroll
            for (int kk = 0; kk < 4; kk++) acc[i][j][kk] = 0.f;

    #pragma unroll
    for (int ch = 0; ch < NSTAGE-1; ch++){
        load_chunk(ch, ch);
        asm volatile("cp.async.commit_group;" ::: "memory");
    }

    for (int ch = 0; ch < NCHUNK; ch++){
        const int w = NCHUNK - 1 - ch;
        if (w >= 6)      asm volatile("cp.async.wait_group 6;" ::: "memory");
        else if (w == 5) asm volatile("cp.async.wait_group 5;" ::: "memory");
        else if (w == 4) asm volatile("cp.async.wait_group 4;" ::: "memory");
        else if (w == 3) asm volatile("cp.async.wait_group 3;" ::: "memory");
        else if (w == 2) asm volatile("cp.async.wait_group 2;" ::: "memory");
        else if (w == 1) asm volatile("cp.async.wait_group 1;" ::: "memory");
        else             asm volatile("cp.async.wait_group 0;" ::: "memory");
        __syncthreads();

        const int nxt = ch + NSTAGE - 1;
        if (nxt < NCHUNK){
            load_chunk(nxt, nxt & (NSTAGE-1));
            asm volatile("cp.async.commit_group;" ::: "memory");
        }

        const unsigned int* Ab = smem + (size_t)(ch & (NSTAGE-1)) * STAGE_W;
        const unsigned int* Bb = Ab + A_STAGE_W;
        #pragma unroll
        for (int ks = 0; ks < 2; ks++){           // two k16 steps (kp 0..7, 8..15)
            const int kb = ks*8;
            unsigned af[4][4], bf[8][2];
            const unsigned int* A0 = Ab + (kb + tig    )*APITCH + wm*64;
            const unsigned int* A1 = Ab + (kb + tig + 4)*APITCH + wm*64;
            #pragma unroll
            for (int mt = 0; mt < 4; mt++){
                int mr = mt*16 + g;
                af[mt][0] = A0[mr];
                af[mt][1] = A0[mr + 8];
                af[mt][2] = A1[mr];
                af[mt][3] = A1[mr + 8];
            }
            const unsigned int* B0 = Bb + (kb + tig    )*BPITCH + wn*64;
            const unsigned int* B1 = Bb + (kb + tig + 4)*BPITCH + wn*64;
            #pragma unroll
            for (int nt = 0; nt < 8; nt++){
                int nc = nt*8 + g;
                bf[nt][0] = B0[nc];
                bf[nt][1] = B1[nc];
            }
            #pragma unroll
            for (int mt = 0; mt < 4; mt++)
                #pragma unroll
                for (int nt = 0; nt < 8; nt++)
                    mma_f16(acc[mt][nt], af[mt], bf[nt]);
        }
    }

    // epilogue (accumulator layout identical to R3's)
    #pragma unroll
    for (int mt = 0; mt < 4; mt++){
        int r0 = m0 + wm*64 + mt*16 + g;
        size_t mb = (size_t)(r0 & 4095);
        #pragma unroll
        for (int nt = 0; nt < 8; nt++){
            int oc = n0 + wn*64 + nt*8 + 2*tig;
            float b0 = __ldg(bias + oc), b1 = __ldg(bias + oc + 1);
            size_t base = (((size_t)(nimg*COUT + oc)) << 12) + mb;
            out[base           ] = acc[mt][nt][0] + b0;
            out[base + 4096    ] = acc[mt][nt][1] + b1;
            out[base + 8       ] = acc[mt][nt][2] + b0;
            out[base + 4096 + 8] = acc[mt][nt][3] + b1;
        }
    }
}

// ---------------- launch ----------------
extern "C" void kernel_launch(void* const* d_in, const int* in_sizes, int n_in,
                              void* d_out, int out_size){
    const float* x    = (const float*)d_in[0];
    const float* w    = (const float*)d_in[1];
    const float* bias = (const float*)d_in[2];
    const float* bk   = (const float*)d_in[3];
    float* out = (float*)d_out;
    (void)in_sizes; (void)n_in; (void)out_size;

    {
        long total = (long)NPP*33*129;
        int blocks = (int)((total + 255) / 256);
        blur_kernel<<<blocks, 256>>>(x, bk);
    }
    wtrans_kernel<<<(9*128*512 + 255)/256, 256>>>(w);

    const int SMEM = NSTAGE * STAGE_W * 4;  // 204800 bytes
    cudaFuncSetAttribute(conv_kernel, cudaFuncAttributeMaxDynamicSharedMemorySize, SMEM);
    conv_kernel<<<dim3(COUT/BN, (NIMG*64*64)/BM), 256, SMEM>>>(bias, out);
}

// round 7
// speedup vs baseline: 2.3664x; 1.0746x over previous
#include <cuda_runtime.h>
#include <cuda_fp16.h>
#include <cstdint>
#include <cstddef>

// ---------------- problem constants ----------------
#define NIMG   16
#define CIN    256
#define COUT   512
#define HIN    128
#define OHB    129
#define WPLANE (OHB*64)       // 8256 half2-words per (n, c-pair) plane
#define NPP    2048           // 16 images * 128 channel-pairs

// GEMM tiling: K = 1152 k-pairs total (9 taps * 128 pairs), 32 pairs (64 elems) per chunk
#define NCHUNK 36
#define BM 256                // pixels
#define BN 128                // output channels
#define APITCH 264            // words; 264 % 32 == 8 -> conflict-free
#define BPITCH 136            // words
#define NSTAGE 4
#define A_STAGE_W (32*APITCH)              // 8448 words
#define B_STAGE_W (32*BPITCH)              // 4352 words
#define STAGE_W   (A_STAGE_W + B_STAGE_W)  // 12800 words = 51200 B

// ---------------- device scratch ----------------
__device__ __align__(16) unsigned int g_xbE [(size_t)NPP*WPLANE];
__device__ __align__(16) unsigned int g_xbO [(size_t)NPP*WPLANE];
__device__ __align__(16) unsigned int g_xbE2[(size_t)NPP*WPLANE];
__device__ __align__(16) unsigned int g_Bw[9*128*COUT];   // [tap][c-pair][oc] half2

// ---------------- kernel 1: separable 4x4 blur, 8 outputs/thread ----------------
__global__ void blur_kernel(const float* __restrict__ x, const float* __restrict__ bk){
    const unsigned XG = 129, YG = 17;   // 17*8 = 136 >= 129 rows
    unsigned id = blockIdx.x * blockDim.x + threadIdx.x;
    const unsigned total = (unsigned)NPP*YG*XG;
    if (id >= total) return;
    unsigned xc = id % XG;
    unsigned r  = id / XG;
    unsigned yg = r % YG;
    unsigned pp = r / YG;            // plane-pair: n*128 + c2

    float C0=__ldg(bk+0), C1=__ldg(bk+1), C2=__ldg(bk+2), C3=__ldg(bk+3);
    float inv = 1.0f / C0;
    float R1=__ldg(bk+4)*inv, R2=__ldg(bk+8)*inv, R3=__ldg(bk+12)*inv;

    const float* xp0 = x + (size_t)pp * 2 * (HIN*HIN);
    const float* xp1 = xp0 + HIN*HIN;
    int y0 = (int)yg * 8;
    int cb = (int)xc - 2;

    bool b0 = (cb+0 >= 0 && cb+0 < HIN);
    bool b1 = (cb+1 >= 0 && cb+1 < HIN);
    bool b2 = (cb+2 >= 0 && cb+2 < HIN);
    bool b3 = (cb+3 >= 0 && cb+3 < HIN);

    float cs0[11], cs1[11];
    #pragma unroll
    for (int rr = 0; rr < 11; rr++){
        int row = y0 - 2 + rr;
        float v0 = 0.f, v1 = 0.f;
        if (row >= 0 && row < HIN){
            const float* rp0 = xp0 + row*HIN;
            const float* rp1 = xp1 + row*HIN;
            float p00 = b0 ? __ldg(rp0+cb+0) : 0.f;
            float p01 = b1 ? __ldg(rp0+cb+1) : 0.f;
            float p02 = b2 ? __ldg(rp0+cb+2) : 0.f;
            float p03 = b3 ? __ldg(rp0+cb+3) : 0.f;
            float p10 = b0 ? __ldg(rp1+cb+0) : 0.f;
            float p11 = b1 ? __ldg(rp1+cb+1) : 0.f;
            float p12 = b2 ? __ldg(rp1+cb+2) : 0.f;
            float p13 = b3 ? __ldg(rp1+cb+3) : 0.f;
            v0 = p00*C0 + p01*C1 + p02*C2 + p03*C3;
            v1 = p10*C0 + p11*C1 + p12*C2 + p13*C3;
        }
        cs0[rr] = v0; cs1[rr] = v1;
    }

    unsigned int* pe  = g_xbE  + (size_t)pp * WPLANE;
    unsigned int* po  = g_xbO  + (size_t)pp * WPLANE;
    unsigned int* pe2 = g_xbE2 + (size_t)pp * WPLANE;
    unsigned h = xc >> 1;
    #pragma unroll
    for (int i = 0; i < 8; i++){
        int y = y0 + i;
        if (y < OHB){
            float v0 = cs0[i] + R1*cs0[i+1] + R2*cs0[i+2] + R3*cs0[i+3];
            float v1 = cs1[i] + R1*cs1[i+1] + R2*cs1[i+2] + R3*cs1[i+3];
            __half2 hv = __floats2half2_rn(v0, v1);
            unsigned int w = *reinterpret_cast<unsigned int*>(&hv);
            unsigned rb = (unsigned)y * 64;
            if ((xc & 1u) == 0u){
                if (h < 64) pe[rb + h] = w;
                if (xc >= 2) pe2[rb + h - 1] = w;
            } else {
                po[rb + h] = w;
            }
        }
    }
}

// ---------------- kernel 2: weight repack half2 [tap][c-pair][oc] ----------------
__global__ void wtrans_kernel(const float* __restrict__ w){
    unsigned id = blockIdx.x * blockDim.x + threadIdx.x;
    if (id >= 9u*128u*512u) return;
    unsigned oc  = id & 511u;
    unsigned kp  = (id >> 9) & 127u;
    unsigned tap = id >> 16;
    unsigned s = tap / 3, t = tap - 3*s;
    const float scale = 0.0208333333333333333f;  // 1/sqrt(2304)
    unsigned c0 = kp*2, c1 = kp*2 + 1;
    float v0 = __ldg(&w[((size_t)(oc*CIN + c0)*3 + s)*3 + t]) * scale;
    float v1 = __ldg(&w[((size_t)(oc*CIN + c1)*3 + s)*3 + t]) * scale;
    __half2 hv = __floats2half2_rn(v0, v1);
    g_Bw[id] = *reinterpret_cast<unsigned int*>(&hv);
}

// ---------------- kernel 3: implicit GEMM conv (fp16 mma, fp32 accum) ----------------
__device__ __forceinline__ void mma_f16(float c[4], const unsigned a[4], const unsigned b[2]){
    asm volatile(
        "mma.sync.aligned.m16n8k16.row.col.f32.f16.f16.f32 "
        "{%0,%1,%2,%3}, {%4,%5,%6,%7}, {%8,%9}, {%0,%1,%2,%3};\n"
        : "+f"(c[0]), "+f"(c[1]), "+f"(c[2]), "+f"(c[3])
        : "r"(a[0]), "r"(a[1]), "r"(a[2]), "r"(a[3]), "r"(b[0]), "r"(b[1]));
}

#define CP16(dst, src) \
    asm volatile("cp.async.cg.shared.global [%0], [%1], 16;\n" :: "r"(dst), "l"(src))

__global__ void __launch_bounds__(256, 1)
conv_kernel(const float* __restrict__ bias, float* __restrict__ out){
    extern __shared__ unsigned int smem[];

    const int tid  = threadIdx.x;
    const int lane = tid & 31, warp = tid >> 5;
    const int n0   = blockIdx.x * BN;
    const int m0   = blockIdx.y * BM;
    const int nimg = m0 >> 12;
    const int p0   = (m0 & 4095) >> 6;            // 4 output rows per block
    const int g    = lane >> 2, tig = lane & 3;
    const int wm   = warp & 3,  wn  = warp >> 2;  // 4x2 warps -> 64x64 warp tile

    const uint32_t sbase = (uint32_t)__cvta_generic_to_shared(smem);
    const size_t pb2 = (size_t)nimg * 128;

    // chunk ch (0..35): tap = ch>>2, c-pair base = (ch&3)*32
    auto load_chunk = [&](int ch, int stage){
        const int tap = ch >> 2;
        const int cb2 = (ch & 3) << 5;
        const int s   = tap / 3;
        const int t   = tap - 3*s;
        const unsigned int* ab = (t == 0) ? g_xbE : (t == 1 ? g_xbO : g_xbE2);
        const uint32_t stg = sbase + (uint32_t)stage * (STAGE_W*4);
        // A: pixels [32 kp][256 m] half2 words
        #pragma unroll
        for (int i = 0; i < 8; i++){
            int gid = i*256 + tid;
            int kp  = gid >> 6;                   // 0..31
            int mg  = gid & 63;
            int pl  = mg >> 4;
            int q4  = (mg & 15) << 2;
            const unsigned int* src = ab + (pb2 + cb2 + kp)*WPLANE
                                    + (size_t)(2*(p0 + pl) + s)*64 + q4;
            CP16(stg + (uint32_t)((kp*APITCH + mg*4) << 2), src);
        }
        // B: weights [32 kp][128 oc] half2 words
        #pragma unroll
        for (int i = 0; i < 4; i++){
            int gid = i*256 + tid;
            int kp  = gid >> 5;                   // 0..31
            int ng  = gid & 31;
            const unsigned int* src = g_Bw + ((size_t)tap*128 + cb2 + kp)*COUT + n0 + ng*4;
            CP16(stg + (uint32_t)((A_STAGE_W + kp*BPITCH + ng*4) << 2), src);
        }
    };

    float acc[4][8][4];
    #pragma unroll
    for (int i = 0; i < 4; i++)
        #pragma unroll
        for (int j = 0; j < 8; j++)
            #pragma unroll
            for (int kk = 0; kk < 4; kk++) acc[i][j][kk] = 0.f;

    #pragma unroll
    for (int ch = 0; ch < NSTAGE-1; ch++){
        load_chunk(ch, ch);
        asm volatile("cp.async.commit_group;" ::: "memory");
    }

    unsigned af[2][4][4], bf[2][8][2];

    for (int ch = 0; ch < NCHUNK; ch++){
        if (ch <= NCHUNK-3)      asm volatile("cp.async.wait_group 2;" ::: "memory");
        else if (ch == NCHUNK-2) asm volatile("cp.async.wait_group 1;" ::: "memory");
        else                     asm volatile("cp.async.wait_group 0;" ::: "memory");
        __syncthreads();

        const int nxt = ch + NSTAGE - 1;
        if (nxt < NCHUNK){
            load_chunk(nxt, nxt & (NSTAGE-1));
            asm volatile("cp.async.commit_group;" ::: "memory");
        }

        const unsigned int* Ab = smem + (size_t)(ch & (NSTAGE-1)) * STAGE_W;
        const unsigned int* Bb = Ab + A_STAGE_W;

        // fragment loader for k-step ks (8 kp rows) into buffer buf
        auto ldfrag = [&](int ks, int buf){
            const int kb = ks*8;
            const unsigned int* A0 = Ab + (kb + tig    )*APITCH + wm*64;
            const unsigned int* A1 = Ab + (kb + tig + 4)*APITCH + wm*64;
            #pragma unroll
            for (int mt = 0; mt < 4; mt++){
                int mr = mt*16 + g;
                af[buf][mt][0] = A0[mr];
                af[buf][mt][1] = A0[mr + 8];
                af[buf][mt][2] = A1[mr];
                af[buf][mt][3] = A1[mr + 8];
            }
            const unsigned int* B0 = Bb + (kb + tig    )*BPITCH + wn*64;
            const unsigned int* B1 = Bb + (kb + tig + 4)*BPITCH + wn*64;
            #pragma unroll
            for (int nt = 0; nt < 8; nt++){
                int nc = nt*8 + g;
                bf[buf][nt][0] = B0[nc];
                bf[buf][nt][1] = B1[nc];
            }
        };

        ldfrag(0, 0);
        #pragma unroll
        for (int ks = 0; ks < 4; ks++){
            const int cur = ks & 1;
            if (ks < 3) ldfrag(ks + 1, cur ^ 1);
            #pragma unroll
            for (int mt = 0; mt < 4; mt++)
                #pragma unroll
                for (int nt = 0; nt < 8; nt++)
                    mma_f16(acc[mt][nt], af[cur][mt], bf[cur][nt]);
        }
    }

    // epilogue
    #pragma unroll
    for (int mt = 0; mt < 4; mt++){
        int r0 = m0 + wm*64 + mt*16 + g;
        size_t mb = (size_t)(r0 & 4095);
        #pragma unroll
        for (int nt = 0; nt < 8; nt++){
            int oc = n0 + wn*64 + nt*8 + 2*tig;
            float b0 = __ldg(bias + oc), b1 = __ldg(bias + oc + 1);
            size_t base = (((size_t)(nimg*COUT + oc)) << 12) + mb;
            out[base           ] = acc[mt][nt][0] + b0;
            out[base + 4096    ] = acc[mt][nt][1] + b1;
            out[base + 8       ] = acc[mt][nt][2] + b0;
            out[base + 4096 + 8] = acc[mt][nt][3] + b1;
        }
    }
}

// ---------------- launch ----------------
extern "C" void kernel_launch(void* const* d_in, const int* in_sizes, int n_in,
                              void* d_out, int out_size){
    const float* x    = (const float*)d_in[0];
    const float* w    = (const float*)d_in[1];
    const float* bias = (const float*)d_in[2];
    const float* bk   = (const float*)d_in[3];
    float* out = (float*)d_out;
    (void)in_sizes; (void)n_in; (void)out_size;

    {
        long total = (long)NPP*17*129;
        int blocks = (int)((total + 255) / 256);
        blur_kernel<<<blocks, 256>>>(x, bk);
    }
    wtrans_kernel<<<(9*128*512 + 255)/256, 256>>>(w);

    const int SMEM = NSTAGE * STAGE_W * 4;  // 204800 bytes
    cudaFuncSetAttribute(conv_kernel, cudaFuncAttributeMaxDynamicSharedMemorySize, SMEM);
    conv_kernel<<<dim3(COUT/BN, (NIMG*64*64)/BM), 256, SMEM>>>(bias, out);
}

// round 12
// speedup vs baseline: 2.7830x; 1.1760x over previous
#include <cuda_runtime.h>
#include <cuda_fp16.h>
#include <cstdint>
#include <cstddef>

// ---------------- problem constants ----------------
#define NIMG   16
#define CIN    256
#define COUT   512
#define HIN    128
#define OHB    129
#define WPLANE (OHB*64)       // 8256 half2-words per (n, c-pair) plane
#define NPP    2048           // 16 images * 128 channel-pairs

// GEMM tiling: K = 1152 k-pairs total (9 taps * 128 pairs), 32 pairs (64 elems) per chunk
#define NCHUNK 36
#define BM 256                // pixels
#define BN 128                // output channels
#define APITCH 264            // words; 264 % 32 == 8 -> conflict-free
#define BPITCH 136            // words
#define NSTAGE 4
#define A_STAGE_W (32*APITCH)              // 8448 words
#define B_STAGE_W (32*BPITCH)              // 4352 words
#define STAGE_W   (A_STAGE_W + B_STAGE_W)  // 12800 words = 51200 B

// ---------------- device scratch ----------------
__device__ __align__(16) unsigned int g_xbE [(size_t)NPP*WPLANE];
__device__ __align__(16) unsigned int g_xbO [(size_t)NPP*WPLANE];
__device__ __align__(16) unsigned int g_xbE2[(size_t)NPP*WPLANE];
__device__ __align__(16) unsigned int g_Bw[9*128*COUT];   // [tap][c-pair][oc] half2

// ---------------- kernel 1: warp-streaming separable blur ----------------
// One warp per plane-pair. Lane l owns columns 4l..4l+3 (LDG.128 per plane per row).
// Horizontal 4-tap FIR via shuffles; vertical 4-tap via a 4-deep register ring.
__global__ void __launch_bounds__(128, 4)
blur_kernel(const float* __restrict__ x, const float* __restrict__ bk){
    const int warp = (int)(blockIdx.x * 4 + (threadIdx.x >> 5));   // plane-pair id
    const int l    = threadIdx.x & 31;
    if (warp >= NPP) return;

    const float C0=__ldg(bk+0), C1=__ldg(bk+1), C2=__ldg(bk+2), C3=__ldg(bk+3);
    const float inv = 1.0f / C0;
    const float R1=__ldg(bk+4)*inv, R2=__ldg(bk+8)*inv, R3=__ldg(bk+12)*inv;

    const float4* xp0 = (const float4*)(x + (size_t)warp * 2 * (HIN*HIN)) + l;
    const float4* xp1 = xp0 + (HIN*HIN/4);

    unsigned int* pe  = g_xbE  + (size_t)warp * WPLANE;
    unsigned int* po  = g_xbO  + (size_t)warp * WPLANE;
    unsigned int* pe2 = g_xbE2 + (size_t)warp * WPLANE;

    float hA[4][4], hB[4][4];    // vertical ring: [row&3][col 0..3], planes A/B
    float h4A[4], h4B[4];        // lane31's col-128 ring
    #pragma unroll
    for (int s = 0; s < 4; s++){
        #pragma unroll
        for (int c = 0; c < 4; c++){ hA[s][c] = 0.f; hB[s][c] = 0.f; }
        h4A[s] = 0.f; h4B[s] = 0.f;
    }

    const bool l0 = (l == 0), l31 = (l == 31);

    for (int rb = 0; rb < 132; rb += 4){
        #pragma unroll
        for (int j = 0; j < 4; j++){
            const int r = rb + j;
            // ---- load row r (zero rows beyond the image) ----
            float4 a0 = make_float4(0.f,0.f,0.f,0.f), a1 = a0;
            if (r < HIN){
                a0 = __ldg(xp0 + r*32);
                a1 = __ldg(xp1 + r*32);
            }
            // ---- halo shuffles ----
            float xm2A = __shfl_up_sync(0xffffffffu, a0.z, 1);
            float xm1A = __shfl_up_sync(0xffffffffu, a0.w, 1);
            float xp4A = __shfl_down_sync(0xffffffffu, a0.x, 1);
            float xm2B = __shfl_up_sync(0xffffffffu, a1.z, 1);
            float xm1B = __shfl_up_sync(0xffffffffu, a1.w, 1);
            float xp4B = __shfl_down_sync(0xffffffffu, a1.x, 1);
            if (l0){ xm2A = 0.f; xm1A = 0.f; xm2B = 0.f; xm1B = 0.f; }
            if (l31){ xp4A = 0.f; xp4B = 0.f; }
            // ---- horizontal FIR: out col 4l+c uses inputs (4l+c-2 .. 4l+c+1) ----
            hA[j][0] = xm2A*C0 + xm1A*C1 + a0.x*C2 + a0.y*C3;
            hA[j][1] = xm1A*C0 + a0.x*C1 + a0.y*C2 + a0.z*C3;
            hA[j][2] = a0.x*C0 + a0.y*C1 + a0.z*C2 + a0.w*C3;
            hA[j][3] = a0.y*C0 + a0.z*C1 + a0.w*C2 + xp4A*C3;
            hB[j][0] = xm2B*C0 + xm1B*C1 + a1.x*C2 + a1.y*C3;
            hB[j][1] = xm1B*C0 + a1.x*C1 + a1.y*C2 + a1.z*C3;
            hB[j][2] = a1.x*C0 + a1.y*C1 + a1.z*C2 + a1.w*C3;
            hB[j][3] = a1.y*C0 + a1.z*C1 + a1.w*C2 + xp4B*C3;
            // col 128 (lane31 only meaningful): inputs 126,127 (128,129 are zero)
            h4A[j] = a0.z*C0 + a0.w*C1;
            h4B[j] = a1.z*C0 + a1.w*C1;

            // ---- emit output row y = r-1 (needs input rows r-3..r) ----
            if (r >= 1 && r <= 129){
                const int y = r - 1;
                const int s0 = (j+1)&3, s1 = (j+2)&3, s2 = (j+3)&3, s3 = j;
                float vA[4], vB[4];
                #pragma unroll
                for (int c = 0; c < 4; c++){
                    vA[c] = hA[s0][c] + R1*hA[s1][c] + R2*hA[s2][c] + R3*hA[s3][c];
                    vB[c] = hB[s0][c] + R1*hB[s1][c] + R2*hB[s2][c] + R3*hB[s3][c];
                }
                __half2 wE0h = __floats2half2_rn(vA[0], vB[0]);
                __half2 wO0h = __floats2half2_rn(vA[1], vB[1]);
                __half2 wE1h = __floats2half2_rn(vA[2], vB[2]);
                __half2 wO1h = __floats2half2_rn(vA[3], vB[3]);
                unsigned int wE0 = *(unsigned int*)&wE0h;
                unsigned int wO0 = *(unsigned int*)&wO0h;
                unsigned int wE1 = *(unsigned int*)&wE1h;
                unsigned int wO1 = *(unsigned int*)&wO1h;

                const unsigned rb64 = (unsigned)y * 64u;
                // pe: even cols 4l, 4l+2 -> h = 2l, 2l+1 (8B store)
                *(uint2*)(pe + rb64 + 2*l) = make_uint2(wE0, wE1);
                // po: odd cols 4l+1, 4l+3 -> h = 2l, 2l+1
                *(uint2*)(po + rb64 + 2*l) = make_uint2(wO0, wO1);
                // pe2[h-1]: col 4l -> pe2[2l-1] (skip lane0 col 0), col 4l+2 -> pe2[2l]
                if (!l0) pe2[rb64 + 2*l - 1] = wE0;
                pe2[rb64 + 2*l] = wE1;
                if (l31){
                    float v128A = h4A[s0] + R1*h4A[s1] + R2*h4A[s2] + R3*h4A[s3];
                    float v128B = h4B[s0] + R1*h4B[s1] + R2*h4B[s2] + R3*h4B[s3];
                    __half2 w128h = __floats2half2_rn(v128A, v128B);
                    pe2[rb64 + 63] = *(unsigned int*)&w128h;
                }
            }
        }
    }
}

// ---------------- kernel 2: weight repack half2 [tap][c-pair][oc] ----------------
__global__ void wtrans_kernel(const float* __restrict__ w){
    unsigned id = blockIdx.x * blockDim.x + threadIdx.x;
    if (id >= 9u*128u*512u) return;
    unsigned oc  = id & 511u;
    unsigned kp  = (id >> 9) & 127u;
    unsigned tap = id >> 16;
    unsigned s = tap / 3, t = tap - 3*s;
    const float scale = 0.0208333333333333333f;  // 1/sqrt(2304)
    unsigned c0 = kp*2, c1 = kp*2 + 1;
    float v0 = __ldg(&w[((size_t)(oc*CIN + c0)*3 + s)*3 + t]) * scale;
    float v1 = __ldg(&w[((size_t)(oc*CIN + c1)*3 + s)*3 + t]) * scale;
    __half2 hv = __floats2half2_rn(v0, v1);
    g_Bw[id] = *reinterpret_cast<unsigned int*>(&hv);
}

// ---------------- kernel 3: implicit GEMM conv (fp16 mma, fp32 accum) ----------------
__device__ __forceinline__ void mma_f16(float c[4], const unsigned a[4], const unsigned b[2]){
    asm volatile(
        "mma.sync.aligned.m16n8k16.row.col.f32.f16.f16.f32 "
        "{%0,%1,%2,%3}, {%4,%5,%6,%7}, {%8,%9}, {%0,%1,%2,%3};\n"
        : "+f"(c[0]), "+f"(c[1]), "+f"(c[2]), "+f"(c[3])
        : "r"(a[0]), "r"(a[1]), "r"(a[2]), "r"(a[3]), "r"(b[0]), "r"(b[1]));
}

#define CP16(dst, src) \
    asm volatile("cp.async.cg.shared.global [%0], [%1], 16;\n" :: "r"(dst), "l"(src))

__global__ void __launch_bounds__(256, 1)
conv_kernel(const float* __restrict__ bias, float* __restrict__ out){
    extern __shared__ unsigned int smem[];

    const int tid  = threadIdx.x;
    const int lane = tid & 31, warp = tid >> 5;
    const int n0   = blockIdx.x * BN;
    const int m0   = blockIdx.y * BM;
    const int nimg = m0 >> 12;
    const int p0   = (m0 & 4095) >> 6;            // 4 output rows per block
    const int g    = lane >> 2, tig = lane & 3;
    const int wm   = warp & 3,  wn  = warp >> 2;  // 4x2 warps -> 64x64 warp tile

    const uint32_t sbase = (uint32_t)__cvta_generic_to_shared(smem);
    const size_t pb2 = (size_t)nimg * 128;

    // chunk ch (0..35): tap = ch>>2, c-pair base = (ch&3)*32
    auto load_chunk = [&](int ch, int stage){
        const int tap = ch >> 2;
        const int cb2 = (ch & 3) << 5;
        const int s   = tap / 3;
        const int t   = tap - 3*s;
        const unsigned int* ab = (t == 0) ? g_xbE : (t == 1 ? g_xbO : g_xbE2);
        const uint32_t stg = sbase + (uint32_t)stage * (STAGE_W*4);
        // A: pixels [32 kp][256 m] half2 words
        #pragma unroll
        for (int i = 0; i < 8; i++){
            int gid = i*256 + tid;
            int kp  = gid >> 6;                   // 0..31
            int mg  = gid & 63;
            int pl  = mg >> 4;
            int q4  = (mg & 15) << 2;
            const unsigned int* src = ab + (pb2 + cb2 + kp)*WPLANE
                                    + (size_t)(2*(p0 + pl) + s)*64 + q4;
            CP16(stg + (uint32_t)((kp*APITCH + mg*4) << 2), src);
        }
        // B: weights [32 kp][128 oc] half2 words
        #pragma unroll
        for (int i = 0; i < 4; i++){
            int gid = i*256 + tid;
            int kp  = gid >> 5;                   // 0..31
            int ng  = gid & 31;
            const unsigned int* src = g_Bw + ((size_t)tap*128 + cb2 + kp)*COUT + n0 + ng*4;
            CP16(stg + (uint32_t)((A_STAGE_W + kp*BPITCH + ng*4) << 2), src);
        }
    };

    float acc[4][8][4];
    #pragma unroll
    for (int i = 0; i < 4; i++)
        #pragma unroll
        for (int j = 0; j < 8; j++)
            #pragma unroll
            for (int kk = 0; kk < 4; kk++) acc[i][j][kk] = 0.f;

    #pragma unroll
    for (int ch = 0; ch < NSTAGE-1; ch++){
        load_chunk(ch, ch);
        asm volatile("cp.async.commit_group;" ::: "memory");
    }

    unsigned af[2][4][4], bf[2][8][2];

    for (int ch = 0; ch < NCHUNK; ch++){
        if (ch <= NCHUNK-3)      asm volatile("cp.async.wait_group 2;" ::: "memory");
        else if (ch == NCHUNK-2) asm volatile("cp.async.wait_group 1;" ::: "memory");
        else                     asm volatile("cp.async.wait_group 0;" ::: "memory");
        __syncthreads();

        const int nxt = ch + NSTAGE - 1;
        if (nxt < NCHUNK){
            load_chunk(nxt, nxt & (NSTAGE-1));
            asm volatile("cp.async.commit_group;" ::: "memory");
        }

        const unsigned int* Ab = smem + (size_t)(ch & (NSTAGE-1)) * STAGE_W;
        const unsigned int* Bb = Ab + A_STAGE_W;

        auto ldfrag = [&](int ks, int buf){
            const int kb = ks*8;
            const unsigned int* A0 = Ab + (kb + tig    )*APITCH + wm*64;
            const unsigned int* A1 = Ab + (kb + tig + 4)*APITCH + wm*64;
            #pragma unroll
            for (int mt = 0; mt < 4; mt++){
                int mr = mt*16 + g;
                af[buf][mt][0] = A0[mr];
                af[buf][mt][1] = A0[mr + 8];
                af[buf][mt][2] = A1[mr];
                af[buf][mt][3] = A1[mr + 8];
            }
            const unsigned int* B0 = Bb + (kb + tig    )*BPITCH + wn*64;
            const unsigned int* B1 = Bb + (kb + tig + 4)*BPITCH + wn*64;
            #pragma unroll
            for (int nt = 0; nt < 8; nt++){
                int nc = nt*8 + g;
                bf[buf][nt][0] = B0[nc];
                bf[buf][nt][1] = B1[nc];
            }
        };

        ldfrag(0, 0);
        #pragma unroll
        for (int ks = 0; ks < 4; ks++){
            const int cur = ks & 1;
            if (ks < 3) ldfrag(ks + 1, cur ^ 1);
            #pragma unroll
            for (int mt = 0; mt < 4; mt++)
                #pragma unroll
                for (int nt = 0; nt < 8; nt++)
                    mma_f16(acc[mt][nt], af[cur][mt], bf[cur][nt]);
        }
    }

    // epilogue
    #pragma unroll
    for (int mt = 0; mt < 4; mt++){
        int r0 = m0 + wm*64 + mt*16 + g;
        size_t mb = (size_t)(r0 & 4095);
        #pragma unroll
        for (int nt = 0; nt < 8; nt++){
            int oc = n0 + wn*64 + nt*8 + 2*tig;
            float b0 = __ldg(bias + oc), b1 = __ldg(bias + oc + 1);
            size_t base = (((size_t)(nimg*COUT + oc)) << 12) + mb;
            out[base           ] = acc[mt][nt][0] + b0;
            out[base + 4096    ] = acc[mt][nt][1] + b1;
            out[base + 8       ] = acc[mt][nt][2] + b0;
            out[base + 4096 + 8] = acc[mt][nt][3] + b1;
        }
    }
}

// ---------------- launch ----------------
extern "C" void kernel_launch(void* const* d_in, const int* in_sizes, int n_in,
                              void* d_out, int out_size){
    const float* x    = (const float*)d_in[0];
    const float* w    = (const float*)d_in[1];
    const float* bias = (const float*)d_in[2];
    const float* bk   = (const float*)d_in[3];
    float* out = (float*)d_out;
    (void)in_sizes; (void)n_in; (void)out_size;

    blur_kernel<<<NPP/4, 128>>>(x, bk);
    wtrans_kernel<<<(9*128*512 + 255)/256, 256>>>(w);

    const int SMEM = NSTAGE * STAGE_W * 4;  // 204800 bytes
    cudaFuncSetAttribute(conv_kernel, cudaFuncAttributeMaxDynamicSharedMemorySize, SMEM);
    conv_kernel<<<dim3(COUT/BN, (NIMG*64*64)/BM), 256, SMEM>>>(bias, out);
}